// round 17
// baseline (speedup 1.0000x reference)
#include <cuda_runtime.h>

// PZCell biquad, warp-per-row parallel scan, PAIRED quarters with packed
// f32x2 math (FFMA2): qa/qb chains vectorized 2-wide in Phase A and in the
// store-correction. Scan stays scalar (shfl is 32-bit).
// y[t] = b0 x[t] + b1 x[t-1] + b2 x[t-2] - a1 y[t-1] - a2 y[t-2]   (den == 1)
// Matrix powers as Cayley-Hamilton k-pairs: M^n = k1*M - k2*I.

namespace {
constexpr int T_LEN   = 2048;
constexpr int B_ROWS  = 4096;
constexpr int QSTEPS  = 512;                // steps per quarter
constexpr int QTILE   = 512;                // floats per quarter buffer (2KB)
constexpr int RPB     = 2;                  // rows (warps) per block
constexpr int THREADS = 32 * RPB;
constexpr int WARP_SMEM  = 4 * QTILE;       // 4 resident quarter buffers
constexpr int SMEM_BYTES = RPB * WARP_SMEM * (int)sizeof(float);  // 16384
}

// chunk c (0..31, 16 floats), granule g (0..3): conflict-free for all passes
__device__ __forceinline__ int swz(int c, int g) {
    return c * 16 + ((g ^ ((c >> 1) & 3)) << 2);
}

__device__ __forceinline__ void cp_async16(float* dst, const float* src) {
    unsigned s = (unsigned)__cvta_generic_to_shared(dst);
    asm volatile("cp.async.cg.shared.global [%0], [%1], 16;" :: "r"(s), "l"(src));
}
__device__ __forceinline__ void cp_commit() { asm volatile("cp.async.commit_group;"); }
template <int N>
__device__ __forceinline__ void cp_wait() {
    asm volatile("cp.async.wait_group %0;" :: "n"(N) : "memory");
}

// ---- packed f32x2 (maps to FFMA2 / wide MUL on sm_103a) ----
struct F2 { unsigned long long v; };
__device__ __forceinline__ F2 pack2(float lo, float hi) {
    F2 r; asm("mov.b64 %0, {%1, %2};" : "=l"(r.v) : "f"(lo), "f"(hi)); return r;
}
__device__ __forceinline__ void unpack2(F2 a, float& lo, float& hi) {
    asm("mov.b64 {%0, %1}, %2;" : "=f"(lo), "=f"(hi) : "l"(a.v));
}
__device__ __forceinline__ F2 fma2(F2 a, F2 b, F2 c) {
    F2 r; asm("fma.rn.f32x2 %0, %1, %2, %3;" : "=l"(r.v) : "l"(a.v), "l"(b.v), "l"(c.v)); return r;
}
__device__ __forceinline__ F2 mul2(F2 a, F2 b) {
    F2 r; asm("mul.rn.f32x2 %0, %1, %2;" : "=l"(r.v) : "l"(a.v), "l"(b.v)); return r;
}

struct Coef { float a1, a2; };
struct K2   { float k1, k2; };   // k1*M - k2*I
// broadcast coefficient pairs for the packed paths
struct CoefP { F2 B0, B1, B2, nA1, nA2, A2, Bc; };

__device__ __forceinline__ K2 ksq(K2 a, float a1, float a2) {
    float t = a.k1 * a.k1;
    K2 r;
    r.k1 = -fmaf(a1, t, 2.f * a.k1 * a.k2);
    r.k2 =  fmaf(a2, t, -a.k2 * a.k2);
    return r;
}
__device__ __forceinline__ K2 kmul(K2 p, K2 q, float a1, float a2) {
    float t = p.k1 * q.k1;
    K2 r;
    r.k1 = -fmaf(a1, t, fmaf(p.k1, q.k2, p.k2 * q.k1));
    r.k2 =  fmaf(a2, t, -p.k2 * q.k2);
    return r;
}

__device__ __forceinline__ void issue_quarter_load(
    float* buf, const float* __restrict__ xq, int lane)
{
    #pragma unroll
    for (int k = 0; k < 4; ++k) {
        int ch = k * 8 + (lane >> 2);
        cp_async16(buf + swz(ch, lane & 3), xq + k * 128 + lane * 4);
    }
    cp_commit();
}

// one pair of quarters (qa = even, qb = odd): packed Phase A, interleaved
// scalar scans, packed fused-correction store.
template <bool BUILD>
__device__ __forceinline__ void pair_pass(
    float* bA, float* bB, float* __restrict__ yA, float* __restrict__ yB,
    int lane, const Coef& c, const CoefP& P2, F2 Wp1, F2 WnP2, K2 M16k,
    K2& A, K2& M512k, float& Px, float& Py, float& bx1, float& bx2)
{
    const float a1 = c.a1, a2 = c.a2;

    // ---- boundaries (all reads before any Phase A writes) ----
    float x1a, x2a, x1b, x2b;
    if (lane > 0) {
        int cc = lane - 1;
        int off = cc * 16 + ((3 ^ ((cc >> 1) & 3)) << 2);
        x1a = bA[off + 3];  x2a = bA[off + 2];
        x1b = bB[off + 3];  x2b = bB[off + 2];
    } else {
        x1a = bx1; x2a = bx2;
        x1b = bA[496 + 3];  x2b = bA[496 + 2];   // qa tail (chunk 31, g3 -> 496)
        bx1 = bB[496 + 3];  bx2 = bB[496 + 2];   // carry x tail for next pair
    }
    __syncwarp();

    // ---- Phase A: both quarters packed as f32x2 lanes (lo=qa, hi=qb) ----
    F2 Xm1 = pack2(x1a, x1b);
    F2 Xm2 = pack2(x2a, x2b);
    F2 Pp  = pack2(0.f, 0.f);
    F2 Qp  = pack2(0.f, 0.f);
    #pragma unroll
    for (int g = 0; g < 4; ++g) {
        float4 xva = *reinterpret_cast<float4*>(bA + swz(lane, g));
        float4 xvb = *reinterpret_cast<float4*>(bB + swz(lane, g));
        F2 X0 = pack2(xva.x, xvb.x);
        F2 X1 = pack2(xva.y, xvb.y);
        F2 X2 = pack2(xva.z, xvb.z);
        F2 X3 = pack2(xva.w, xvb.w);
        F2 u0 = fma2(P2.B0, X0, fma2(P2.B1, Xm1, mul2(P2.B2, Xm2)));
        F2 u1 = fma2(P2.B0, X1, fma2(P2.B1, X0,  mul2(P2.B2, Xm1)));
        F2 u2 = fma2(P2.B0, X2, fma2(P2.B1, X1,  mul2(P2.B2, X0)));
        F2 u3 = fma2(P2.B0, X3, fma2(P2.B1, X2,  mul2(P2.B2, X1)));
        Xm2 = X2; Xm1 = X3;
        F2 w1 = fma2(P2.nA1, u0, u1);
        F2 w3 = fma2(P2.nA1, u2, u3);
        F2 zA = fma2(P2.nA1, Pp, fma2(P2.nA2, Qp, u0));
        F2 zB = fma2(P2.A2,  Pp, fma2(P2.Bc,  Qp, w1));
        F2 zC = fma2(P2.nA1, zB, fma2(P2.nA2, zA, u2));
        F2 zD = fma2(P2.A2,  zB, fma2(P2.Bc,  zA, w3));
        Pp = zD; Qp = zC;
        float4 za, zb;
        unpack2(zA, za.x, zb.x);
        unpack2(zB, za.y, zb.y);
        unpack2(zC, za.z, zb.z);
        unpack2(zD, za.w, zb.w);
        *reinterpret_cast<float4*>(bA + swz(lane, g)) = za;
        *reinterpret_cast<float4*>(bB + swz(lane, g)) = zb;
    }
    float pa, pb, qa, qb;
    unpack2(Pp, pa, pb);
    unpack2(Qp, qa, qb);

    // ---- two interleaved scalar Kogge-Stone scans, shared ksq chain ----
    K2 m = M16k;
    float vax = pa, vay = qa, vbx = pb, vby = qb;
    if (lane == 0) {   // seed qa with row carry: d0' = d0 + M16*P
        float t = fmaf(-a1, Px, -a2 * Py);
        vax = fmaf(m.k1, t,  fmaf(-m.k2, Px, vax));
        vay = fmaf(m.k1, Px, fmaf(-m.k2, Py, vay));
    }
    if (BUILD) A = K2{ 0.f, -1.f };   // identity
    #pragma unroll
    for (int i = 0; i < 5; ++i) {
        int d = 1 << i;
        float oax = __shfl_up_sync(0xffffffffu, vax, d);
        float oay = __shfl_up_sync(0xffffffffu, vay, d);
        float obx = __shfl_up_sync(0xffffffffu, vbx, d);
        float oby = __shfl_up_sync(0xffffffffu, vby, d);
        if (lane >= d) {
            float ta = fmaf(-a1, oax, -a2 * oay);
            vax = fmaf(m.k1, ta,  fmaf(-m.k2, oax, vax));
            vay = fmaf(m.k1, oax, fmaf(-m.k2, oay, vay));
            float tb = fmaf(-a1, obx, -a2 * oby);
            vbx = fmaf(m.k1, tb,  fmaf(-m.k2, obx, vbx));
            vby = fmaf(m.k1, obx, fmaf(-m.k2, oby, vby));
        }
        if (BUILD && ((lane >> i) & 1)) A = kmul(m, A, a1, a2);
        if (i < 4) m = ksq(m, a1, a2);
    }
    if (BUILD) M512k = ksq(m, a1, a2);   // m = M^256 after loop

    // ---- entries and carries ----
    float eax = __shfl_up_sync(0xffffffffu, vax, 1);
    float eay = __shfl_up_sync(0xffffffffu, vay, 1);
    if (lane == 0) { eax = Px; eay = Py; }             // qa entries (true)
    float ebx = __shfl_up_sync(0xffffffffu, vbx, 1);
    float eby = __shfl_up_sync(0xffffffffu, vby, 1);
    if (lane == 0) { ebx = 0.f; eby = 0.f; }           // qb zero-entry entries
    // C = true exit of qa (seed carried it)
    float Cx = __shfl_sync(0xffffffffu, vax, 31);
    float Cy = __shfl_sync(0xffffffffu, vay, 31);
    // qb true entries: E = A_lane * C + e0
    {
        float t = fmaf(-a1, Cx, -a2 * Cy);
        ebx = fmaf(A.k1, t,  fmaf(-A.k2, Cx, ebx));
        eby = fmaf(A.k1, Cx, fmaf(-A.k2, Cy, eby));
    }
    // pair exit: P' = M512 * C + D_b
    float Dbx = __shfl_sync(0xffffffffu, vbx, 31);
    float Dby = __shfl_sync(0xffffffffu, vby, 31);
    {
        float t = fmaf(-a1, Cx, -a2 * Cy);
        Px = fmaf(M512k.k1, t,  fmaf(-M512k.k2, Cx, Dbx));
        Py = fmaf(M512k.k1, Cx, fmaf(-M512k.k2, Cy, Dby));
    }
    __syncwarp();   // Phase A z writes visible before transposed reads

    // ---- packed fused-correction coalesced stores (both quarters) ----
    // pos = k*128 + lane*4: chunk ch = 8k + (lane>>2), f0 = (lane&3)*4,
    // seed = W*E per quarter, W = M^f0 as k-pair (Wp1, -Wp2) broadcast pairs.
    #pragma unroll
    for (int k = 0; k < 4; ++k) {
        int ch = k * 8 + (lane >> 2);
        float eA1 = __shfl_sync(0xffffffffu, eax, ch);
        float eA2 = __shfl_sync(0xffffffffu, eay, ch);
        float eB1 = __shfl_sync(0xffffffffu, ebx, ch);
        float eB2 = __shfl_sync(0xffffffffu, eby, ch);
        F2 Ex = pack2(eA1, eB1);
        F2 Ey = pack2(eA2, eB2);
        F2 t  = fma2(P2.nA1, Ex, mul2(P2.nA2, Ey));
        F2 s1 = fma2(Wp1, t,  mul2(WnP2, Ex));
        F2 s2 = fma2(Wp1, Ex, mul2(WnP2, Ey));
        F2 hA = fma2(P2.nA1, s1, mul2(P2.nA2, s2));
        F2 hB = fma2(P2.A2,  s1, mul2(P2.Bc,  s2));
        F2 hC = fma2(P2.nA1, hB, mul2(P2.nA2, hA));
        F2 hD = fma2(P2.A2,  hB, mul2(P2.Bc,  hA));
        float hAa, hAb, hBa, hBb, hCa, hCb, hDa, hDb;
        unpack2(hA, hAa, hAb);
        unpack2(hB, hBa, hBb);
        unpack2(hC, hCa, hCb);
        unpack2(hD, hDa, hDb);
        float4 zva = *reinterpret_cast<float4*>(bA + swz(ch, lane & 3));
        zva.x += hAa; zva.y += hBa; zva.z += hCa; zva.w += hDa;
        *reinterpret_cast<float4*>(yA + k * 128 + lane * 4) = zva;
        float4 zvb = *reinterpret_cast<float4*>(bB + swz(ch, lane & 3));
        zvb.x += hAb; zvb.y += hBb; zvb.z += hCb; zvb.w += hDb;
        *reinterpret_cast<float4*>(yB + k * 128 + lane * 4) = zvb;
    }
    __syncwarp();
}

__global__ void __launch_bounds__(THREADS, 13)
pzH_kernel(const float* __restrict__ x, const float* __restrict__ gain_ri,
           const float* __restrict__ poles_ri, const float* __restrict__ zeros_ri,
           float* __restrict__ out)
{
    extern __shared__ float sbuf[];
    const int lane = threadIdx.x & 31;
    const int w    = threadIdx.x >> 5;
    const int row  = blockIdx.x * RPB + w;
    const float* xr = x   + (long)row * T_LEN;
    float*       yr = out + (long)row * T_LEN;
    float* sb = sbuf + w * WARP_SMEM;

    // ---- issue all 4 quarter loads up front (4 commit groups) ----
    issue_quarter_load(sb + 0 * QTILE, xr + 0 * QSTEPS, lane);
    issue_quarter_load(sb + 1 * QTILE, xr + 1 * QSTEPS, lane);
    issue_quarter_load(sb + 2 * QTILE, xr + 2 * QSTEPS, lane);
    issue_quarter_load(sb + 3 * QTILE, xr + 3 * QSTEPS, lane);

    // ---- coefficients + k-pair powers (overlap with cp.async) ----
    Coef c;
    float b0, b1, b2, A2s, Bcs;
    {
        const float gr = gain_ri[0],  gi = gain_ri[1];
        const float pr0 = poles_ri[0], pi0 = poles_ri[1];
        const float pr1 = poles_ri[2], pi1 = poles_ri[3];
        const float zr0 = zeros_ri[0], zi0 = zeros_ri[1];
        const float zr1 = zeros_ri[2], zi1 = zeros_ri[3];
        c.a1 = -(pr0 + pr1);
        c.a2 = pr0 * pr1 - pi0 * pi1;
        const float zc1r = -(zr0 + zr1), zc1i = -(zi0 + zi1);
        const float zc2r = zr0 * zr1 - zi0 * zi1;
        const float zc2i = zr0 * zi1 + zi0 * zr1;
        b0 = gr;
        b1 = gr * zc1r - gi * zc1i;
        b2 = gr * zc2r - gi * zc2i;
        A2s = c.a1 * c.a1 - c.a2;
        Bcs = c.a1 * c.a2;
    }
    const float a1 = c.a1, a2 = c.a2;
    CoefP P2;
    P2.B0  = pack2(b0, b0);
    P2.B1  = pack2(b1, b1);
    P2.B2  = pack2(b2, b2);
    P2.nA1 = pack2(-a1, -a1);
    P2.nA2 = pack2(-a2, -a2);
    P2.A2  = pack2(A2s, A2s);
    P2.Bc  = pack2(Bcs, Bcs);

    K2 M1k  = { 1.f, 0.f };
    K2 M4k  = ksq(ksq(M1k, a1, a2), a1, a2);
    K2 M8k  = ksq(M4k, a1, a2);
    K2 M16k = ksq(M8k, a1, a2);
    K2 M12k = kmul(M8k, M4k, a1, a2);
    // W = M^(4*(lane&3)) as broadcast pairs (W1, -W2)
    const int j = lane & 3;
    const float W1 = (j == 0) ? 0.f  : (j == 1) ? M4k.k1 : (j == 2) ? M8k.k1 : M12k.k1;
    const float W2 = (j == 0) ? -1.f : (j == 1) ? M4k.k2 : (j == 2) ? M8k.k2 : M12k.k2;
    F2 Wp1  = pack2(W1, W1);
    F2 WnP2 = pack2(-W2, -W2);

    K2 A, M512k;                   // built in first pair, reused in second
    float Px = 0.f, Py = 0.f;      // row exit state carry
    float bx1 = 0.f, bx2 = 0.f;    // x tail carry (lane 0)

    cp_wait<2>(); __syncwarp();    // q0, q1 resident (q2, q3 streaming)
    pair_pass<true>(sb + 0 * QTILE, sb + 1 * QTILE,
                    yr + 0 * QSTEPS, yr + 1 * QSTEPS,
                    lane, c, P2, Wp1, WnP2, M16k, A, M512k, Px, Py, bx1, bx2);

    cp_wait<0>(); __syncwarp();    // q2, q3 resident
    pair_pass<false>(sb + 2 * QTILE, sb + 3 * QTILE,
                     yr + 2 * QSTEPS, yr + 3 * QSTEPS,
                     lane, c, P2, Wp1, WnP2, M16k, A, M512k, Px, Py, bx1, bx2);
}

extern "C" void kernel_launch(void* const* d_in, const int* in_sizes, int n_in,
                              void* d_out, int out_size) {
    (void)in_sizes; (void)n_in; (void)out_size;
    const float* x        = (const float*)d_in[0];
    const float* gain_ri  = (const float*)d_in[1];
    const float* poles_ri = (const float*)d_in[2];
    const float* zeros_ri = (const float*)d_in[3];
    float* out = (float*)d_out;

    cudaFuncSetAttribute(pzH_kernel, cudaFuncAttributeMaxDynamicSharedMemorySize, SMEM_BYTES);
    pzH_kernel<<<B_ROWS / RPB, THREADS, SMEM_BYTES>>>(x, gain_ri, poles_ri, zeros_ri, out);
}